// round 4
// baseline (speedup 1.0000x reference)
#include <cuda_runtime.h>

#define FULLMASK 0xffffffffu
typedef unsigned long long ull;

namespace {
constexpr int BB = 256;
constexpr int TT = 2048;
constexpr int DD = 64;
constexpr int LBAND = 2;
constexpr int DB = 32;
constexpr int GG = 96;
constexpr int PADW = 36;       // padded row stride (floats) -> conflict-free LDS.128
constexpr int TPAD = TT + 32;  // dt rows padded so the 32-wide prefetch never reads OOB
}

// Scratch (module-static device globals; no runtime allocation)
__device__ float g_pdt[LBAND][BB][TPAD];
__device__ int   g_nv[LBAND][BB];
__device__ float g_c0[LBAND][BB][GG];
__device__ float g_c1[LBAND][BB][GG];

// ---------------------------------------------------------------------------
// Kernel 1: stable compaction of valid dtime values per (band,row) + counts
// ---------------------------------------------------------------------------
__global__ void compact_kernel(const int* __restrict__ band_ids,
                               const float* __restrict__ dtime) {
    int warp = threadIdx.x >> 5;
    int lane = threadIdx.x & 31;
    int b = blockIdx.x * (blockDim.x >> 5) + warp;
    if (b >= BB) return;
    int cnt0 = 0, cnt1 = 0;
    for (int base = 0; base < TT; base += 32) {
        int t = base + lane;
        int id = band_ids[b * TT + t];
        float dt = dtime[b * TT + t];
        unsigned m0 = __ballot_sync(FULLMASK, id == 0);
        unsigned lt = (1u << lane) - 1u;
        if (id == 0) {
            g_pdt[0][b][cnt0 + __popc(m0 & lt)] = dt;
        } else {
            g_pdt[1][b][cnt1 + __popc((~m0) & lt)] = dt;
        }
        int p0 = __popc(m0);
        cnt0 += p0;
        cnt1 += 32 - p0;
    }
    if (lane == 0) { g_nv[0][b] = cnt0; g_nv[1][b] = cnt1; }
}

// ---------------------------------------------------------------------------
// Kernel 2: per-(band,row) affine layer-1 gate constants:
//   gx1_t = c0 + dt_t * c1
//   For the r,z gate rows (gi<2) we also fold bhh1 into c0 (legal: they enter
//   as sigmoid(gx+gh)). The n row keeps bhh separate (needed inside r*gh_n).
// ---------------------------------------------------------------------------
__global__ void rowconst_kernel(const float* __restrict__ z_last,
                                const float* __restrict__ proj_W,
                                const float* __restrict__ proj_b,
                                const float* __restrict__ Wih,
                                const float* __restrict__ bih,
                                const float* __restrict__ bhh) {
    int warp = threadIdx.x >> 5;
    int lane = threadIdx.x & 31;
    int wg = blockIdx.x * (blockDim.x >> 5) + warp;
    if (wg >= LBAND * BB) return;
    int kb = wg >> 8;    // / 256
    int b  = wg & 255;

    float base = proj_b[kb * DB + lane];
#pragma unroll 8
    for (int i = 0; i < DD; i++) {
        base = fmaf(z_last[b * DD + i],
                    proj_W[(kb * (DD + 1) + i) * DB + lane], base);
    }
    float w65 = proj_W[(kb * (DD + 1) + DD) * DB + lane];

    for (int gi = 0; gi < 3; gi++) {
        int g = lane + 32 * gi;
        float c0a = bih[(kb * 2 + 0) * GG + g];
        if (gi < 2) c0a += bhh[(kb * 2 + 0) * GG + g];   // fold bhh for r,z only
        float c1a = 0.f;
        for (int j = 0; j < DB; j++) {
            float bj = __shfl_sync(FULLMASK, base, j);
            float wj = __shfl_sync(FULLMASK, w65, j);
            float w  = Wih[((kb * 2 + 0) * GG + g) * DB + j];
            c0a = fmaf(w, bj, c0a);
            c1a = fmaf(w, wj, c1a);
        }
        g_c0[kb][b][g] = c0a;
        g_c1[kb][b][g] = c1a;
    }
}

// ---------------------------------------------------------------------------
// f32x2 helpers
// ---------------------------------------------------------------------------
__device__ __forceinline__ ull ffma2(ull a, ull b, ull c) {
    ull d;
    asm("fma.rn.f32x2 %0, %1, %2, %3;" : "=l"(d) : "l"(a), "l"(b), "l"(c));
    return d;
}
__device__ __forceinline__ float hsum2(ull p) {
    float lo, hi;
    asm("mov.b64 {%0, %1}, %2;" : "=f"(lo), "=f"(hi) : "l"(p));
    return lo + hi;
}
__device__ __forceinline__ ull pack2(float a, float b) {
    ull p;
    asm("mov.b64 %0, {%1, %2};" : "=l"(p) : "f"(a), "f"(b));
    return p;
}
__device__ __forceinline__ float fast_sigmoid(float x) {
    return __fdividef(1.0f, 1.0f + __expf(-x));
}
__device__ __forceinline__ float fast_tanh(float x) {
    return __fdividef(2.0f, 1.0f + __expf(-2.0f * x)) - 1.0f;
}

// ---------------------------------------------------------------------------
// Main GRU kernel: 1 warp per (band,row) sequence; 4 warps/block.
// Whh1/Whh2 register-resident (96 f32 each per lane, as f32x2 pairs).
// Wih2 + MLP weights in smem. h vectors double-buffered in smem rows,
// consumed as LDS.64 broadcasts of (h[2k], h[2k+1]) pairs for fma.f32x2.
// ---------------------------------------------------------------------------
__global__ __launch_bounds__(128, 1)
void gru_main_kernel(const float* __restrict__ Wih,
                     const float* __restrict__ Whh,
                     const float* __restrict__ bih,
                     const float* __restrict__ bhh,
                     const float* __restrict__ mW1,
                     const float* __restrict__ mb1,
                     const float* __restrict__ mW2,
                     const float* __restrict__ mb2,
                     float* __restrict__ out) {
    __shared__ __align__(16) float sWih2[GG][PADW];
    __shared__ __align__(8)  ull   sM1p[DB / 2][DB];   // (mW1[2k][l], mW1[2k+1][l])
    __shared__ __align__(8)  float hb1[2][4][DB];
    __shared__ __align__(8)  float hb2[2][4][DB];

    const int kb   = blockIdx.x >> 6;
    const int bgrp = blockIdx.x & 63;
    const int wid  = threadIdx.x >> 5;
    const int lane = threadIdx.x & 31;
    const int b    = bgrp * 4 + wid;

    // ---- stage smem weights ----
    for (int idx = threadIdx.x; idx < GG * DB; idx += blockDim.x) {
        sWih2[idx >> 5][idx & 31] = Wih[(kb * 2 + 1) * GG * DB + idx];
    }
    for (int idx = threadIdx.x; idx < (DB / 2) * DB; idx += blockDim.x) {
        int k = idx >> 5, l = idx & 31;
        sM1p[k][l] = pack2(mW1[kb * DB * DB + (2 * k) * DB + l],
                           mW1[kb * DB * DB + (2 * k + 1) * DB + l]);
    }
    // init h buffers (both parities) to zero
    hb1[0][wid][lane] = 0.f; hb1[1][wid][lane] = 0.f;
    hb2[0][wid][lane] = 0.f; hb2[1][wid][lane] = 0.f;
    __syncthreads();

    // ---- register-resident Whh1 / Whh2 (rows lane, lane+32, lane+64) ----
    ull w1r[16], w1z[16], w1n[16], w2r[16], w2z[16], w2n[16];
    {
        const ull* p1r = (const ull*)(Whh + ((size_t)((kb * 2 + 0) * GG + lane)      * DB));
        const ull* p1z = (const ull*)(Whh + ((size_t)((kb * 2 + 0) * GG + lane + 32) * DB));
        const ull* p1n = (const ull*)(Whh + ((size_t)((kb * 2 + 0) * GG + lane + 64) * DB));
        const ull* p2r = (const ull*)(Whh + ((size_t)((kb * 2 + 1) * GG + lane)      * DB));
        const ull* p2z = (const ull*)(Whh + ((size_t)((kb * 2 + 1) * GG + lane + 32) * DB));
        const ull* p2n = (const ull*)(Whh + ((size_t)((kb * 2 + 1) * GG + lane + 64) * DB));
#pragma unroll
        for (int k = 0; k < 16; k++) {
            w1r[k] = p1r[k]; w1z[k] = p1z[k]; w1n[k] = p1n[k];
            w2r[k] = p2r[k]; w2z[k] = p2z[k]; w2n[k] = p2n[k];
        }
    }

    // ---- per-lane constants ----
    const float c0r = g_c0[kb][b][lane];
    const float c0z = g_c0[kb][b][lane + 32];
    const float c0n = g_c0[kb][b][lane + 64];
    const float c1r = g_c1[kb][b][lane];
    const float c1z = g_c1[kb][b][lane + 32];
    const float c1n = g_c1[kb][b][lane + 64];
    const float bh1n = bhh[(kb * 2 + 0) * GG + lane + 64];
    const float b2r  = bih[(kb * 2 + 1) * GG + lane]      + bhh[(kb * 2 + 1) * GG + lane];
    const float b2z  = bih[(kb * 2 + 1) * GG + lane + 32] + bhh[(kb * 2 + 1) * GG + lane + 32];
    const float bi2n = bih[(kb * 2 + 1) * GG + lane + 64];
    const float bh2n = bhh[(kb * 2 + 1) * GG + lane + 64];
    const float mb1l = mb1[kb * DB + lane];
    const float mw2l = mW2[kb * DB + lane];
    const float mb2s = mb2[kb];

    const int nv = g_nv[kb][b];
    const float* __restrict__ pdt = &g_pdt[kb][b][0];
    float* __restrict__ orow = out + ((size_t)kb * BB + b) * TT;

    float h1 = 0.f, h2 = 0.f, dtv = 0.f;

    for (int i = 0; i < nv; i++) {
        const int rb = (i + 1) & 1;   // read buffer (written last step)
        const int wb = i & 1;         // write buffer
        if ((i & 31) == 0) dtv = pdt[i + lane];   // TPAD: never OOB
        float dt = __shfl_sync(FULLMASK, dtv, i & 31);

        // ---- both recurrent matvecs from registers (6 f32x2 chains) ----
        ull a1r = 0ull, a1z = 0ull, a1n = 0ull;
        ull a2r = 0ull, a2z = 0ull, a2n = 0ull;
        {
            const ull* hp1 = (const ull*)hb1[rb][wid];
            const ull* hp2 = (const ull*)hb2[rb][wid];
#pragma unroll
            for (int k = 0; k < 16; k++) {
                ull p1 = hp1[k], p2 = hp2[k];   // LDS.64 broadcast
                a1r = ffma2(w1r[k], p1, a1r);
                a1z = ffma2(w1z[k], p1, a1z);
                a1n = ffma2(w1n[k], p1, a1n);
                a2r = ffma2(w2r[k], p2, a2r);
                a2z = ffma2(w2z[k], p2, a2z);
                a2n = ffma2(w2n[k], p2, a2n);
            }
        }

        // ---- layer-1 gates (bhh folded into c0 for r,z) ----
        float r1 = fast_sigmoid(fmaf(dt, c1r, c0r) + hsum2(a1r));
        float z1 = fast_sigmoid(fmaf(dt, c1z, c0z) + hsum2(a1z));
        float n1 = fast_tanh(fmaf(dt, c1n, c0n) + r1 * (hsum2(a1n) + bh1n));
        h1 = fmaf(z1, h1 - n1, n1);
        hb1[wb][wid][lane] = h1;
        __syncwarp();

        // ---- layer-2 input gates: Wih2 @ h1_new (smem weights) ----
        ull g2r = 0ull, g2z = 0ull, g2n = 0ull;
        {
            const ull* hn1 = (const ull*)hb1[wb][wid];
#pragma unroll
            for (int k = 0; k < 8; k++) {
                ull q0 = hn1[2 * k], q1 = hn1[2 * k + 1];
                longlong2 wr = *(const longlong2*)&sWih2[lane][4 * k];
                longlong2 wz = *(const longlong2*)&sWih2[lane + 32][4 * k];
                longlong2 wn = *(const longlong2*)&sWih2[lane + 64][4 * k];
                g2r = ffma2((ull)wr.x, q0, g2r); g2r = ffma2((ull)wr.y, q1, g2r);
                g2z = ffma2((ull)wz.x, q0, g2z); g2z = ffma2((ull)wz.y, q1, g2z);
                g2n = ffma2((ull)wn.x, q0, g2n); g2n = ffma2((ull)wn.y, q1, g2n);
            }
        }

        float r2 = fast_sigmoid(hsum2(g2r) + hsum2(a2r) + b2r);
        float z2 = fast_sigmoid(hsum2(g2z) + hsum2(a2z) + b2z);
        float n2 = fast_tanh((hsum2(g2n) + bi2n) + r2 * (hsum2(a2n) + bh2n));
        h2 = fmaf(z2, h2 - n2, n2);
        hb2[wb][wid][lane] = h2;
        __syncwarp();

        // ---- output MLP (off the recurrence critical path) ----
        ull acc = 0ull;
        {
            const ull* hn2 = (const ull*)hb2[wb][wid];
#pragma unroll
            for (int k = 0; k < 16; k++)
                acc = ffma2(sM1p[k][lane], hn2[k], acc);
        }
        float hid = fmaxf(hsum2(acc) + mb1l, 0.f);
        float p = hid * mw2l;
#pragma unroll
        for (int off = 16; off > 0; off >>= 1)
            p += __shfl_xor_sync(FULLMASK, p, off);
        if (lane == 0) orow[i] = p + mb2s;
    }

    // ---- tail fill: y constant for i >= nv (h frozen on masked steps) ----
    {
        const ull* hf = (const ull*)hb2[(nv + 1) & 1][wid];
        ull acc = 0ull;
#pragma unroll
        for (int k = 0; k < 16; k++)
            acc = ffma2(sM1p[k][lane], hf[k], acc);
        float hid = fmaxf(hsum2(acc) + mb1l, 0.f);
        float p = hid * mw2l;
#pragma unroll
        for (int off = 16; off > 0; off >>= 1)
            p += __shfl_xor_sync(FULLMASK, p, off);
        float y = p + mb2s;                    // butterfly leaves sum in all lanes
        for (int idx = nv + lane; idx < TT; idx += 32) orow[idx] = y;
    }
}

// ---------------------------------------------------------------------------
extern "C" void kernel_launch(void* const* d_in, const int* in_sizes, int n_in,
                              void* d_out, int out_size) {
    const int*   band_ids = (const int*)  d_in[0];
    const float* dtime    = (const float*)d_in[1];
    const float* z_last   = (const float*)d_in[2];
    const float* proj_W   = (const float*)d_in[3];
    const float* proj_b   = (const float*)d_in[4];
    const float* Wih      = (const float*)d_in[5];
    const float* Whh      = (const float*)d_in[6];
    const float* bih      = (const float*)d_in[7];
    const float* bhh      = (const float*)d_in[8];
    const float* mW1      = (const float*)d_in[9];
    const float* mb1      = (const float*)d_in[10];
    const float* mW2      = (const float*)d_in[11];
    const float* mb2      = (const float*)d_in[12];
    float* out = (float*)d_out;

    compact_kernel<<<BB / 8, 256>>>(band_ids, dtime);
    rowconst_kernel<<<(LBAND * BB) / 4, 128>>>(z_last, proj_W, proj_b, Wih, bih, bhh);
    gru_main_kernel<<<128, 128>>>(Wih, Whh, bih, bhh, mW1, mb1, mW2, mb2, out);
}

// round 5
// speedup vs baseline: 1.1816x; 1.1816x over previous
#include <cuda_runtime.h>

#define FULLMASK 0xffffffffu
typedef unsigned long long ull;

namespace {
constexpr int BB = 256;
constexpr int TT = 2048;
constexpr int DD = 64;
constexpr int LBAND = 2;
constexpr int DB = 32;
constexpr int GG = 96;
constexpr int PADW = 36;       // padded row stride (floats) -> conflict-free LDS.128
constexpr int TPAD = TT + 64;  // dt rows padded so the 32-wide prefetch never reads OOB
}

// Scratch (module-static device globals; no runtime allocation)
__device__ float g_pdt[LBAND][BB][TPAD];
__device__ int   g_nv[LBAND][BB];
__device__ float g_c0[LBAND][BB][GG];
__device__ float g_c1[LBAND][BB][GG];
__device__ float g_h2[LBAND][BB][TT][DB];   // per-step layer-2 hidden states

// ---------------------------------------------------------------------------
// Kernel 1: stable compaction of valid dtime values per (band,row) + counts
// ---------------------------------------------------------------------------
__global__ void compact_kernel(const int* __restrict__ band_ids,
                               const float* __restrict__ dtime) {
    int warp = threadIdx.x >> 5;
    int lane = threadIdx.x & 31;
    int b = blockIdx.x * (blockDim.x >> 5) + warp;
    if (b >= BB) return;
    int cnt0 = 0, cnt1 = 0;
    for (int base = 0; base < TT; base += 32) {
        int t = base + lane;
        int id = band_ids[b * TT + t];
        float dt = dtime[b * TT + t];
        unsigned m0 = __ballot_sync(FULLMASK, id == 0);
        unsigned lt = (1u << lane) - 1u;
        if (id == 0) {
            g_pdt[0][b][cnt0 + __popc(m0 & lt)] = dt;
        } else {
            g_pdt[1][b][cnt1 + __popc((~m0) & lt)] = dt;
        }
        int p0 = __popc(m0);
        cnt0 += p0;
        cnt1 += 32 - p0;
    }
    if (lane == 0) { g_nv[0][b] = cnt0; g_nv[1][b] = cnt1; }
}

// ---------------------------------------------------------------------------
// Kernel 2: per-(band,row) affine layer-1 gate constants (bhh folded for r,z)
// ---------------------------------------------------------------------------
__global__ void rowconst_kernel(const float* __restrict__ z_last,
                                const float* __restrict__ proj_W,
                                const float* __restrict__ proj_b,
                                const float* __restrict__ Wih,
                                const float* __restrict__ bih,
                                const float* __restrict__ bhh) {
    int warp = threadIdx.x >> 5;
    int lane = threadIdx.x & 31;
    int wg = blockIdx.x * (blockDim.x >> 5) + warp;
    if (wg >= LBAND * BB) return;
    int kb = wg >> 8;
    int b  = wg & 255;

    float base = proj_b[kb * DB + lane];
#pragma unroll 8
    for (int i = 0; i < DD; i++) {
        base = fmaf(z_last[b * DD + i],
                    proj_W[(kb * (DD + 1) + i) * DB + lane], base);
    }
    float w65 = proj_W[(kb * (DD + 1) + DD) * DB + lane];

    for (int gi = 0; gi < 3; gi++) {
        int g = lane + 32 * gi;
        float c0a = bih[(kb * 2 + 0) * GG + g];
        if (gi < 2) c0a += bhh[(kb * 2 + 0) * GG + g];
        float c1a = 0.f;
        for (int j = 0; j < DB; j++) {
            float bj = __shfl_sync(FULLMASK, base, j);
            float wj = __shfl_sync(FULLMASK, w65, j);
            float w  = Wih[((kb * 2 + 0) * GG + g) * DB + j];
            c0a = fmaf(w, bj, c0a);
            c1a = fmaf(w, wj, c1a);
        }
        g_c0[kb][b][g] = c0a;
        g_c1[kb][b][g] = c1a;
    }
}

// ---------------------------------------------------------------------------
// f32x2 helpers
// ---------------------------------------------------------------------------
__device__ __forceinline__ ull ffma2(ull a, ull b, ull c) {
    ull d;
    asm("fma.rn.f32x2 %0, %1, %2, %3;" : "=l"(d) : "l"(a), "l"(b), "l"(c));
    return d;
}
__device__ __forceinline__ float hsum2(ull p) {
    float lo, hi;
    asm("mov.b64 {%0, %1}, %2;" : "=f"(lo), "=f"(hi) : "l"(p));
    return lo + hi;
}
__device__ __forceinline__ ull pack2(float a, float b) {
    ull p;
    asm("mov.b64 %0, {%1, %2};" : "=l"(p) : "f"(a), "f"(b));
    return p;
}
__device__ __forceinline__ float fast_sigmoid(float x) {
    return __fdividef(1.0f, 1.0f + __expf(-x));
}
__device__ __forceinline__ float fast_tanh(float x) {
    return __fdividef(2.0f, 1.0f + __expf(-2.0f * x)) - 1.0f;
}

// ---------------------------------------------------------------------------
// Main GRU kernel: 1 warp per (band,row) sequence; layers software-pipelined
// one step apart so L2(i) and L1(i+1) latency chains overlap. No MLP here.
// ---------------------------------------------------------------------------
__global__ __launch_bounds__(128, 1)
void gru_main_kernel(const float* __restrict__ Wih,
                     const float* __restrict__ Whh,
                     const float* __restrict__ bih,
                     const float* __restrict__ bhh) {
    __shared__ __align__(16) float sWih2[GG][PADW];
    __shared__ __align__(8)  float hb1[4][DB];
    __shared__ __align__(8)  float hb2[4][DB];

    const int kb   = blockIdx.x >> 6;
    const int bgrp = blockIdx.x & 63;
    const int wid  = threadIdx.x >> 5;
    const int lane = threadIdx.x & 31;
    const int b    = bgrp * 4 + wid;

    for (int idx = threadIdx.x; idx < GG * DB; idx += blockDim.x) {
        sWih2[idx >> 5][idx & 31] = Wih[(kb * 2 + 1) * GG * DB + idx];
    }
    hb1[wid][lane] = 0.f;
    hb2[wid][lane] = 0.f;
    __syncthreads();

    // Register-resident Whh1 / Whh2 (rows lane, lane+32, lane+64) as f32x2
    ull w1r[16], w1z[16], w1n[16], w2r[16], w2z[16], w2n[16];
    {
        const ull* p1r = (const ull*)(Whh + ((size_t)((kb * 2 + 0) * GG + lane)      * DB));
        const ull* p1z = (const ull*)(Whh + ((size_t)((kb * 2 + 0) * GG + lane + 32) * DB));
        const ull* p1n = (const ull*)(Whh + ((size_t)((kb * 2 + 0) * GG + lane + 64) * DB));
        const ull* p2r = (const ull*)(Whh + ((size_t)((kb * 2 + 1) * GG + lane)      * DB));
        const ull* p2z = (const ull*)(Whh + ((size_t)((kb * 2 + 1) * GG + lane + 32) * DB));
        const ull* p2n = (const ull*)(Whh + ((size_t)((kb * 2 + 1) * GG + lane + 64) * DB));
#pragma unroll
        for (int k = 0; k < 16; k++) {
            w1r[k] = p1r[k]; w1z[k] = p1z[k]; w1n[k] = p1n[k];
            w2r[k] = p2r[k]; w2z[k] = p2z[k]; w2n[k] = p2n[k];
        }
    }

    const float c0r = g_c0[kb][b][lane];
    const float c0z = g_c0[kb][b][lane + 32];
    const float c0n = g_c0[kb][b][lane + 64];
    const float c1r = g_c1[kb][b][lane];
    const float c1z = g_c1[kb][b][lane + 32];
    const float c1n = g_c1[kb][b][lane + 64];
    const float bh1n = bhh[(kb * 2 + 0) * GG + lane + 64];
    const float b2r  = bih[(kb * 2 + 1) * GG + lane]      + bhh[(kb * 2 + 1) * GG + lane];
    const float b2z  = bih[(kb * 2 + 1) * GG + lane + 32] + bhh[(kb * 2 + 1) * GG + lane + 32];
    const float bi2n = bih[(kb * 2 + 1) * GG + lane + 64];
    const float bh2n = bhh[(kb * 2 + 1) * GG + lane + 64];

    const int nv = g_nv[kb][b];
    const float* __restrict__ pdt = &g_pdt[kb][b][0];
    float* __restrict__ h2row = &g_h2[kb][b][0][0];

    float h1 = 0.f, h2 = 0.f;

    // Prologue: L1 step 0 with h1=0 (recurrent terms vanish except bhh_n)
    float dtv = pdt[lane];
    {
        float dt0 = __shfl_sync(FULLMASK, dtv, 0);
        float r1 = fast_sigmoid(fmaf(dt0, c1r, c0r));
        float z1 = fast_sigmoid(fmaf(dt0, c1z, c0z));
        float n1 = fast_tanh(fmaf(dt0, c1n, c0n) + r1 * bh1n);
        h1 = (1.f - z1) * n1;
        hb1[wid][lane] = h1;
    }
    __syncwarp();

    for (int i = 0; i < nv; i++) {
        // dt for step i+1 (prefetch window shifted by one)
        if (((i + 1) & 31) == 0) dtv = pdt[i + 1 + lane];   // TPAD: never OOB
        float dt_next = __shfl_sync(FULLMASK, dtv, (i + 1) & 31);

        // Three interleaved matvecs: a1 = Whh1@h1[i], a2 = Whh2@h2[i-1],
        // g2 = Wih2@h1[i].  a1 and (a2,g2) feed independent gate chains.
        ull a1r = 0ull, a1z = 0ull, a1n = 0ull;
        ull a2r = 0ull, a2z = 0ull, a2n = 0ull;
        ull g2r = 0ull, g2z = 0ull, g2n = 0ull;
        {
            const ull* hp1 = (const ull*)hb1[wid];
            const ull* hp2 = (const ull*)hb2[wid];
#pragma unroll
            for (int k2 = 0; k2 < 8; k2++) {
                ull p1a = hp1[2 * k2], p1b = hp1[2 * k2 + 1];
                ull p2a = hp2[2 * k2], p2b = hp2[2 * k2 + 1];
                longlong2 wr = *(const longlong2*)&sWih2[lane][4 * k2];
                longlong2 wz = *(const longlong2*)&sWih2[lane + 32][4 * k2];
                longlong2 wn = *(const longlong2*)&sWih2[lane + 64][4 * k2];
                a1r = ffma2(w1r[2 * k2], p1a, a1r); a1r = ffma2(w1r[2 * k2 + 1], p1b, a1r);
                a1z = ffma2(w1z[2 * k2], p1a, a1z); a1z = ffma2(w1z[2 * k2 + 1], p1b, a1z);
                a1n = ffma2(w1n[2 * k2], p1a, a1n); a1n = ffma2(w1n[2 * k2 + 1], p1b, a1n);
                a2r = ffma2(w2r[2 * k2], p2a, a2r); a2r = ffma2(w2r[2 * k2 + 1], p2b, a2r);
                a2z = ffma2(w2z[2 * k2], p2a, a2z); a2z = ffma2(w2z[2 * k2 + 1], p2b, a2z);
                a2n = ffma2(w2n[2 * k2], p2a, a2n); a2n = ffma2(w2n[2 * k2 + 1], p2b, a2n);
                g2r = ffma2((ull)wr.x, p1a, g2r);   g2r = ffma2((ull)wr.y, p1b, g2r);
                g2z = ffma2((ull)wz.x, p1a, g2z);   g2z = ffma2((ull)wz.y, p1b, g2z);
                g2n = ffma2((ull)wn.x, p1a, g2n);   g2n = ffma2((ull)wn.y, p1b, g2n);
            }
        }

        // Layer-2 gates for step i (independent of layer-1 chain below)
        float r2 = fast_sigmoid(hsum2(g2r) + hsum2(a2r) + b2r);
        float z2 = fast_sigmoid(hsum2(g2z) + hsum2(a2z) + b2z);
        float n2 = fast_tanh((hsum2(g2n) + bi2n) + r2 * (hsum2(a2n) + bh2n));
        float h2n_ = fmaf(z2, h2 - n2, n2);

        // Layer-1 gates for step i+1
        float r1 = fast_sigmoid(fmaf(dt_next, c1r, c0r) + hsum2(a1r));
        float z1 = fast_sigmoid(fmaf(dt_next, c1z, c0z) + hsum2(a1z));
        float n1 = fast_tanh(fmaf(dt_next, c1n, c0n) + r1 * (hsum2(a1n) + bh1n));
        float h1n_ = fmaf(z1, h1 - n1, n1);

        h2 = h2n_;
        h1 = h1n_;
        h2row[(size_t)i * DB + lane] = h2;    // coalesced 128B, no dependents
        hb1[wid][lane] = h1;
        hb2[wid][lane] = h2;
        __syncwarp();
    }
}

// ---------------------------------------------------------------------------
// Pass 2: massively parallel output MLP. lane j of each warp computes
// y[t0+j] = relu(h2[t']@mW1 + mb1)@mW2 + mb2 with t' = min(t0+j, nv-1)
// (tail steps hold h). 32768 warps -> latency fully hidden.
// ---------------------------------------------------------------------------
__global__ __launch_bounds__(128)
void mlp_kernel(const float* __restrict__ mW1,
                const float* __restrict__ mb1,
                const float* __restrict__ mW2,
                const float* __restrict__ mb2,
                float* __restrict__ out) {
    __shared__ __align__(8) ull   sM1p[DB / 2][DB];   // (mW1[2k][l], mW1[2k+1][l])
    __shared__ __align__(8) float sh[4][32][34];      // per-warp h2 tile, padded
    __shared__ float smb1[DB], smw2[DB];

    const int row = blockIdx.x >> 4;     // 0..511 = kb*256 + b
    const int tg  = blockIdx.x & 15;
    const int kb  = row >> 8;
    const int b   = row & 255;
    const int wid  = threadIdx.x >> 5;
    const int lane = threadIdx.x & 31;

    for (int idx = threadIdx.x; idx < (DB / 2) * DB; idx += blockDim.x) {
        int k = idx >> 5, l = idx & 31;
        sM1p[k][l] = pack2(mW1[kb * DB * DB + (2 * k) * DB + l],
                           mW1[kb * DB * DB + (2 * k + 1) * DB + l]);
    }
    if (threadIdx.x < DB) {
        smb1[threadIdx.x] = mb1[kb * DB + threadIdx.x];
        smw2[threadIdx.x] = mW2[kb * DB + threadIdx.x];
    }
    __syncthreads();

    const int nv = g_nv[kb][b];
    const int t0 = (tg * 4 + wid) * 32;
    const float* __restrict__ hbase = &g_h2[kb][b][0][0];

    // Stage 32 h2 rows (tail rows replaced by the last valid row; zeros if nv==0)
    for (int j = 0; j < 32; j++) {
        int t = t0 + j;
        int src = (t < nv) ? t : (nv - 1);
        float v = (nv > 0) ? hbase[(size_t)src * DB + lane] : 0.f;
        sh[wid][j][lane] = v;
    }
    __syncwarp();

    // lane computes output t0+lane; its h row is register-cached across l
    const ull* hrow = (const ull*)&sh[wid][lane][0];
    ull hr[16];
#pragma unroll
    for (int k = 0; k < 16; k++) hr[k] = hrow[k];

    float y = mb2[kb];
    for (int l = 0; l < DB; l++) {
        ull acc = 0ull;
#pragma unroll
        for (int k = 0; k < 16; k++)
            acc = ffma2(sM1p[k][l], hr[k], acc);
        float hid = fmaxf(hsum2(acc) + smb1[l], 0.f);
        y = fmaf(hid, smw2[l], y);
    }
    out[(size_t)row * TT + t0 + lane] = y;
}

// ---------------------------------------------------------------------------
extern "C" void kernel_launch(void* const* d_in, const int* in_sizes, int n_in,
                              void* d_out, int out_size) {
    const int*   band_ids = (const int*)  d_in[0];
    const float* dtime    = (const float*)d_in[1];
    const float* z_last   = (const float*)d_in[2];
    const float* proj_W   = (const float*)d_in[3];
    const float* proj_b   = (const float*)d_in[4];
    const float* Wih      = (const float*)d_in[5];
    const float* Whh      = (const float*)d_in[6];
    const float* bih      = (const float*)d_in[7];
    const float* bhh      = (const float*)d_in[8];
    const float* mW1      = (const float*)d_in[9];
    const float* mb1      = (const float*)d_in[10];
    const float* mW2      = (const float*)d_in[11];
    const float* mb2      = (const float*)d_in[12];
    float* out = (float*)d_out;

    compact_kernel<<<BB / 8, 256>>>(band_ids, dtime);
    rowconst_kernel<<<(LBAND * BB) / 4, 128>>>(z_last, proj_W, proj_b, Wih, bih, bhh);
    gru_main_kernel<<<128, 128>>>(Wih, Whh, bih, bhh);
    mlp_kernel<<<LBAND * BB * 16, 128>>>(mW1, mb1, mW2, mb2, out);
}

// round 6
// speedup vs baseline: 2.4044x; 2.0349x over previous
#include <cuda_runtime.h>

#define FULLMASK 0xffffffffu
typedef unsigned long long ull;

namespace {
constexpr int BB = 256;
constexpr int TT = 2048;
constexpr int DD = 64;
constexpr int LBAND = 2;
constexpr int DB = 32;
constexpr int GG = 96;
constexpr int TPAD = TT + 64;  // dt rows padded so the 32-wide prefetch never reads OOB
}

// Scratch (module-static device globals; no runtime allocation)
__device__ float g_pdt[LBAND][BB][TPAD];
__device__ int   g_nv[LBAND][BB];
__device__ float g_c0[LBAND][BB][GG];
__device__ float g_c1[LBAND][BB][GG];
__device__ float g_h2[LBAND][BB][TT][DB];   // per-step layer-2 hidden states

// ---------------------------------------------------------------------------
// Kernel 1: stable compaction of valid dtime values per (band,row) + counts
// ---------------------------------------------------------------------------
__global__ void compact_kernel(const int* __restrict__ band_ids,
                               const float* __restrict__ dtime) {
    int warp = threadIdx.x >> 5;
    int lane = threadIdx.x & 31;
    int b = blockIdx.x * (blockDim.x >> 5) + warp;
    if (b >= BB) return;
    int cnt0 = 0, cnt1 = 0;
    for (int base = 0; base < TT; base += 32) {
        int t = base + lane;
        int id = band_ids[b * TT + t];
        float dt = dtime[b * TT + t];
        unsigned m0 = __ballot_sync(FULLMASK, id == 0);
        unsigned lt = (1u << lane) - 1u;
        if (id == 0) {
            g_pdt[0][b][cnt0 + __popc(m0 & lt)] = dt;
        } else {
            g_pdt[1][b][cnt1 + __popc((~m0) & lt)] = dt;
        }
        int p0 = __popc(m0);
        cnt0 += p0;
        cnt1 += 32 - p0;
    }
    if (lane == 0) { g_nv[0][b] = cnt0; g_nv[1][b] = cnt1; }
}

// ---------------------------------------------------------------------------
// Kernel 2: per-(band,row) affine layer-1 gate constants (bhh folded for r,z)
// ---------------------------------------------------------------------------
__global__ void rowconst_kernel(const float* __restrict__ z_last,
                                const float* __restrict__ proj_W,
                                const float* __restrict__ proj_b,
                                const float* __restrict__ Wih,
                                const float* __restrict__ bih,
                                const float* __restrict__ bhh) {
    int warp = threadIdx.x >> 5;
    int lane = threadIdx.x & 31;
    int wg = blockIdx.x * (blockDim.x >> 5) + warp;
    if (wg >= LBAND * BB) return;
    int kb = wg >> 8;
    int b  = wg & 255;

    float base = proj_b[kb * DB + lane];
#pragma unroll 8
    for (int i = 0; i < DD; i++) {
        base = fmaf(z_last[b * DD + i],
                    proj_W[(kb * (DD + 1) + i) * DB + lane], base);
    }
    float w65 = proj_W[(kb * (DD + 1) + DD) * DB + lane];

    for (int gi = 0; gi < 3; gi++) {
        int g = lane + 32 * gi;
        float c0a = bih[(kb * 2 + 0) * GG + g];
        if (gi < 2) c0a += bhh[(kb * 2 + 0) * GG + g];
        float c1a = 0.f;
        for (int j = 0; j < DB; j++) {
            float bj = __shfl_sync(FULLMASK, base, j);
            float wj = __shfl_sync(FULLMASK, w65, j);
            float w  = Wih[((kb * 2 + 0) * GG + g) * DB + j];
            c0a = fmaf(w, bj, c0a);
            c1a = fmaf(w, wj, c1a);
        }
        g_c0[kb][b][g] = c0a;
        g_c1[kb][b][g] = c1a;
    }
}

// ---------------------------------------------------------------------------
// f32x2 helpers
// ---------------------------------------------------------------------------
__device__ __forceinline__ ull ffma2(ull a, ull b, ull c) {
    ull d;
    asm("fma.rn.f32x2 %0, %1, %2, %3;" : "=l"(d) : "l"(a), "l"(b), "l"(c));
    return d;
}
__device__ __forceinline__ float hsum2(ull p) {
    float lo, hi;
    asm("mov.b64 {%0, %1}, %2;" : "=f"(lo), "=f"(hi) : "l"(p));
    return lo + hi;
}
__device__ __forceinline__ ull pack2(float a, float b) {
    ull p;
    asm("mov.b64 %0, {%1, %2};" : "=l"(p) : "f"(a), "f"(b));
    return p;
}
__device__ __forceinline__ float fast_sigmoid(float x) {
    return __fdividef(1.0f, 1.0f + __expf(-x));
}
__device__ __forceinline__ float fast_tanh(float x) {
    return __fdividef(2.0f, 1.0f + __expf(-2.0f * x)) - 1.0f;
}

// ---------------------------------------------------------------------------
// Main GRU kernel: 1 block (2 warps) per (band,row) sequence.
//   Warp A (wid 0): Whh1 + Wih2_r register-resident. Runs layer-1 recurrence
//                   one step ahead; also emits g2r(i) = Wih2_r @ h1(i).
//   Warp B (wid 1): Whh2 + Wih2_z + Wih2_n register-resident. Runs layer-2,
//                   one step behind A (L2 never feeds back into L1).
// Handoff through tiny smem rings; one __syncthreads per step.
// All weight matrices live in registers -> no per-step smem weight traffic,
// and per-warp register demand (<=160 weights + ~40 live) cannot spill.
// ---------------------------------------------------------------------------
__global__ __launch_bounds__(64, 1)
void gru_main_kernel(const float* __restrict__ Wih,
                     const float* __restrict__ Whh,
                     const float* __restrict__ bih,
                     const float* __restrict__ bhh) {
    __shared__ __align__(8) float h1ring[3][DB];
    __shared__ __align__(8) float h2ring[2][DB];
    __shared__ __align__(8) float g2rbuf[2][DB];

    const int row  = blockIdx.x;          // kb*256 + b
    const int kb   = row >> 8;
    const int b    = row & 255;
    const int wid  = threadIdx.x >> 5;
    const int lane = threadIdx.x & 31;

    const int nv = g_nv[kb][b];
    const float* __restrict__ pdt = &g_pdt[kb][b][0];
    float* __restrict__ h2row = &g_h2[kb][b][0][0];

    if (wid == 0) {
        // ================= Warp A: layer 1 =================
        ull w1r[16], w1z[16], w1n[16], wir[16];
        {
            const ull* p1r = (const ull*)(Whh + ((size_t)((kb * 2 + 0) * GG + lane)      * DB));
            const ull* p1z = (const ull*)(Whh + ((size_t)((kb * 2 + 0) * GG + lane + 32) * DB));
            const ull* p1n = (const ull*)(Whh + ((size_t)((kb * 2 + 0) * GG + lane + 64) * DB));
            const ull* pir = (const ull*)(Wih + ((size_t)((kb * 2 + 1) * GG + lane)      * DB));
#pragma unroll
            for (int k = 0; k < 16; k++) {
                w1r[k] = p1r[k]; w1z[k] = p1z[k]; w1n[k] = p1n[k]; wir[k] = pir[k];
            }
        }
        const float c0r = g_c0[kb][b][lane];
        const float c0z = g_c0[kb][b][lane + 32];
        const float c0n = g_c0[kb][b][lane + 64];
        const float c1r = g_c1[kb][b][lane];
        const float c1z = g_c1[kb][b][lane + 32];
        const float c1n = g_c1[kb][b][lane + 64];
        const float bh1n = bhh[(kb * 2 + 0) * GG + lane + 64];

        // Prologue: h1(0) from dt(0) with h=0 (recurrent terms vanish except bh1n)
        float dtv = pdt[lane];
        float dt0 = __shfl_sync(FULLMASK, dtv, 0);
        float r1 = fast_sigmoid(fmaf(dt0, c1r, c0r));
        float z1 = fast_sigmoid(fmaf(dt0, c1z, c0z));
        float n1 = fast_tanh(fmaf(dt0, c1n, c0n) + r1 * bh1n);
        float h1 = (1.f - z1) * n1;
        h1ring[0][lane] = h1;
        __syncthreads();

        int slot = 0;          // = i % 3
        for (int i = 0; i <= nv; i++) {
            if (i < nv) {
                if (((i + 1) & 31) == 0) dtv = pdt[i + 1 + lane];   // TPAD: never OOB
                float dt_next = __shfl_sync(FULLMASK, dtv, (i + 1) & 31);

                const ull* hp = (const ull*)h1ring[slot];           // h1(i)
                ull a1r = 0ull, a1z = 0ull, a1n = 0ull, gr = 0ull;
#pragma unroll
                for (int k = 0; k < 16; k++) {
                    ull p = hp[k];                                  // LDS.64 broadcast
                    a1r = ffma2(w1r[k], p, a1r);
                    a1z = ffma2(w1z[k], p, a1z);
                    a1n = ffma2(w1n[k], p, a1n);
                    gr  = ffma2(wir[k], p, gr);
                }
                r1 = fast_sigmoid(fmaf(dt_next, c1r, c0r) + hsum2(a1r));
                z1 = fast_sigmoid(fmaf(dt_next, c1z, c0z) + hsum2(a1z));
                n1 = fast_tanh(fmaf(dt_next, c1n, c0n) + r1 * (hsum2(a1n) + bh1n));
                h1 = fmaf(z1, h1 - n1, n1);                         // h1(i+1)

                int nslot = slot + 1; if (nslot == 3) nslot = 0;
                h1ring[nslot][lane] = h1;
                g2rbuf[i & 1][lane] = hsum2(gr);                    // g2r(i)
                slot = nslot;
            }
            __syncthreads();
        }
    } else {
        // ================= Warp B: layer 2 (one step behind) =================
        ull w2r[16], w2z[16], w2n[16], wiz[16], win[16];
        {
            const ull* p2r = (const ull*)(Whh + ((size_t)((kb * 2 + 1) * GG + lane)      * DB));
            const ull* p2z = (const ull*)(Whh + ((size_t)((kb * 2 + 1) * GG + lane + 32) * DB));
            const ull* p2n = (const ull*)(Whh + ((size_t)((kb * 2 + 1) * GG + lane + 64) * DB));
            const ull* piz = (const ull*)(Wih + ((size_t)((kb * 2 + 1) * GG + lane + 32) * DB));
            const ull* pin = (const ull*)(Wih + ((size_t)((kb * 2 + 1) * GG + lane + 64) * DB));
#pragma unroll
            for (int k = 0; k < 16; k++) {
                w2r[k] = p2r[k]; w2z[k] = p2z[k]; w2n[k] = p2n[k];
                wiz[k] = piz[k]; win[k] = pin[k];
            }
        }
        const float b2r  = bih[(kb * 2 + 1) * GG + lane]      + bhh[(kb * 2 + 1) * GG + lane];
        const float b2z  = bih[(kb * 2 + 1) * GG + lane + 32] + bhh[(kb * 2 + 1) * GG + lane + 32];
        const float bi2n = bih[(kb * 2 + 1) * GG + lane + 64];
        const float bh2n = bhh[(kb * 2 + 1) * GG + lane + 64];

        h2ring[0][lane] = 0.f;
        h2ring[1][lane] = 0.f;
        float h2 = 0.f;
        __syncthreads();

        int jslot = 2;   // = j % 3 for j = i-1; starts "before" 0 so first j=0 uses slot 0
        for (int i = 0; i <= nv; i++) {
            if (i >= 1) {
                const int j = i - 1;
                jslot = jslot + 1; if (jslot == 3) jslot = 0;        // j % 3
                const ull* hpj = (const ull*)h1ring[jslot];          // h1(j)
                const ull* hp2 = (const ull*)h2ring[(j + 1) & 1];    // h2(j-1)
                ull a2r = 0ull, a2z = 0ull, a2n = 0ull, gz = 0ull, gn = 0ull;
#pragma unroll
                for (int k = 0; k < 16; k++) {
                    ull p1 = hpj[k];
                    ull p2 = hp2[k];
                    a2r = ffma2(w2r[k], p2, a2r);
                    a2z = ffma2(w2z[k], p2, a2z);
                    a2n = ffma2(w2n[k], p2, a2n);
                    gz  = ffma2(wiz[k], p1, gz);
                    gn  = ffma2(win[k], p1, gn);
                }
                float r2 = fast_sigmoid(g2rbuf[j & 1][lane] + hsum2(a2r) + b2r);
                float z2 = fast_sigmoid(hsum2(gz) + hsum2(a2z) + b2z);
                float n2 = fast_tanh(hsum2(gn) + bi2n + r2 * (hsum2(a2n) + bh2n));
                h2 = fmaf(z2, h2 - n2, n2);                          // h2(j)
                h2ring[j & 1][lane] = h2;
                h2row[(size_t)j * DB + lane] = h2;                   // coalesced STG
            }
            __syncthreads();
        }
    }
}

// ---------------------------------------------------------------------------
// Pass 2: massively parallel output MLP with tail skip.
// Tile = 32 consecutive t handled by one warp. Tiles entirely inside the
// valid region compute normally; tiles entirely in the tail exit early; the
// single boundary tile computes y(nv-1) once and broadcast-fills [nv, TT).
// ---------------------------------------------------------------------------
__global__ __launch_bounds__(128)
void mlp_kernel(const float* __restrict__ mW1,
                const float* __restrict__ mb1,
                const float* __restrict__ mW2,
                const float* __restrict__ mb2,
                float* __restrict__ out) {
    __shared__ __align__(8) ull   sM1p[DB / 2][DB];   // (mW1[2k][l], mW1[2k+1][l])
    __shared__ __align__(8) float sh[4][32][34];      // per-warp h2 tile, padded
    __shared__ float smb1[DB], smw2[DB];

    const int row = blockIdx.x >> 4;     // 0..511 = kb*256 + b
    const int tg  = blockIdx.x & 15;
    const int kb  = row >> 8;
    const int b   = row & 255;
    const int wid  = threadIdx.x >> 5;
    const int lane = threadIdx.x & 31;

    for (int idx = threadIdx.x; idx < (DB / 2) * DB; idx += blockDim.x) {
        int k = idx >> 5, l = idx & 31;
        sM1p[k][l] = pack2(mW1[kb * DB * DB + (2 * k) * DB + l],
                           mW1[kb * DB * DB + (2 * k + 1) * DB + l]);
    }
    if (threadIdx.x < DB) {
        smb1[threadIdx.x] = mb1[kb * DB + threadIdx.x];
        smw2[threadIdx.x] = mW2[kb * DB + threadIdx.x];
    }
    __syncthreads();

    const int nv   = g_nv[kb][b];
    const int tile = tg * 4 + wid;       // 0..63
    const int t0   = tile * 32;
    const bool boundary = (tile == (nv >> 5));
    if (t0 >= nv && !boundary) return;   // pure-tail tile: filled by boundary warp

    const float* __restrict__ hbase = &g_h2[kb][b][0][0];

    // Stage 32 h2 rows (tail rows -> last valid row; zeros if nv==0)
    for (int j = 0; j < 32; j++) {
        int t = t0 + j;
        int src = (t < nv) ? t : (nv - 1);
        float v = (nv > 0) ? hbase[(size_t)src * DB + lane] : 0.f;
        sh[wid][j][lane] = v;
    }
    __syncwarp();

    // lane computes output t0+lane; its h row is register-cached across l
    const ull* hrow = (const ull*)&sh[wid][lane][0];
    ull hr[16];
#pragma unroll
    for (int k = 0; k < 16; k++) hr[k] = hrow[k];

    float y = mb2[kb];
#pragma unroll 8
    for (int l = 0; l < DB; l++) {
        ull acc = 0ull;
#pragma unroll
        for (int k = 0; k < 16; k++)
            acc = ffma2(sM1p[k][l], hr[k], acc);
        float hid = fmaxf(hsum2(acc) + smb1[l], 0.f);
        y = fmaf(hid, smw2[l], y);
    }

    float* __restrict__ orow = out + (size_t)row * TT;
    if (!boundary) {
        orow[t0 + lane] = y;             // fully-valid tile
    } else {
        if (t0 + lane < nv) orow[t0 + lane] = y;
        int idx = nv - 1 - t0;           // lane holding y(nv-1)
        idx = idx < 0 ? 0 : (idx > 31 ? 31 : idx);
        float y_last = __shfl_sync(FULLMASK, y, idx);
        for (int t = nv + lane; t < TT; t += 32) orow[t] = y_last;  // tail fill
    }
}

// ---------------------------------------------------------------------------
extern "C" void kernel_launch(void* const* d_in, const int* in_sizes, int n_in,
                              void* d_out, int out_size) {
    const int*   band_ids = (const int*)  d_in[0];
    const float* dtime    = (const float*)d_in[1];
    const float* z_last   = (const float*)d_in[2];
    const float* proj_W   = (const float*)d_in[3];
    const float* proj_b   = (const float*)d_in[4];
    const float* Wih      = (const float*)d_in[5];
    const float* Whh      = (const float*)d_in[6];
    const float* bih      = (const float*)d_in[7];
    const float* bhh      = (const float*)d_in[8];
    const float* mW1      = (const float*)d_in[9];
    const float* mb1      = (const float*)d_in[10];
    const float* mW2      = (const float*)d_in[11];
    const float* mb2      = (const float*)d_in[12];
    float* out = (float*)d_out;

    compact_kernel<<<BB / 8, 256>>>(band_ids, dtime);
    rowconst_kernel<<<(LBAND * BB) / 4, 128>>>(z_last, proj_W, proj_b, Wih, bih, bhh);
    gru_main_kernel<<<LBAND * BB, 64>>>(Wih, Whh, bih, bhh);
    mlp_kernel<<<LBAND * BB * 16, 128>>>(mW1, mb1, mW2, mb2, out);
}